// round 1
// baseline (speedup 1.0000x reference)
#include <cuda_runtime.h>
#include <cuda_bf16.h>
#include <math.h>

// Problem constants
#define Bsz 2
#define Tsz 2048
#define NE 2048
#define NH 16
#define NKV 4
#define DH 128
#define GQ 4
#define QKV_W 3072          // NE + 2*NKV*DH
#define MROWS (Bsz*Tsz)     // 4096

// Scratch (allocation-free rule: __device__ globals)
__device__ float g_qkv[MROWS * QKV_W];   // ~50 MB
__device__ float g_y[MROWS * NE];        // ~34 MB

// ---------------------------------------------------------------------------
// Classic tiled SGEMM: C[M,N] = A[M,K] @ B[K,N], all row-major, fp32.
// 128x128 block tile, BK=8, 256 threads, 8x8 micro-tile. Dims must divide.
// ---------------------------------------------------------------------------
#define BM 128
#define BN 128
#define BK 8
#define TM 8
#define TN 8

__global__ __launch_bounds__(256)
void sgemm_kernel(const float* __restrict__ A, const float* __restrict__ B,
                  float* __restrict__ C, int M, int N, int K) {
    __shared__ float As[BK][BM];
    __shared__ float Bs[BK][BN];

    const int tid = threadIdx.x;
    const int bm = blockIdx.y * BM;
    const int bn = blockIdx.x * BN;

    const int tx = tid & 15;   // 0..15
    const int ty = tid >> 4;   // 0..15

    // global-load mapping
    const int a_row = tid >> 1;          // 0..127
    const int a_col = (tid & 1) * 4;     // 0 or 4
    const int b_row = tid >> 5;          // 0..7
    const int b_col = (tid & 31) * 4;    // 0..124

    float acc[TM][TN];
    #pragma unroll
    for (int i = 0; i < TM; i++)
        #pragma unroll
        for (int j = 0; j < TN; j++) acc[i][j] = 0.f;

    const float* Aptr = A + (size_t)(bm + a_row) * K + a_col;
    const float* Bptr = B + (size_t)b_row * N + bn + b_col;

    for (int k0 = 0; k0 < K; k0 += BK) {
        float4 av = *(const float4*)(Aptr + k0);
        As[a_col + 0][a_row] = av.x;
        As[a_col + 1][a_row] = av.y;
        As[a_col + 2][a_row] = av.z;
        As[a_col + 3][a_row] = av.w;
        float4 bv = *(const float4*)(Bptr + (size_t)k0 * N);
        *(float4*)&Bs[b_row][b_col] = bv;
        __syncthreads();

        #pragma unroll
        for (int kk = 0; kk < BK; kk++) {
            float4 a0 = *(const float4*)&As[kk][ty * TM];
            float4 a1 = *(const float4*)&As[kk][ty * TM + 4];
            float4 b0 = *(const float4*)&Bs[kk][tx * TN];
            float4 b1 = *(const float4*)&Bs[kk][tx * TN + 4];
            float ar[TM] = {a0.x, a0.y, a0.z, a0.w, a1.x, a1.y, a1.z, a1.w};
            float br[TN] = {b0.x, b0.y, b0.z, b0.w, b1.x, b1.y, b1.z, b1.w};
            #pragma unroll
            for (int i = 0; i < TM; i++)
                #pragma unroll
                for (int j = 0; j < TN; j++)
                    acc[i][j] += ar[i] * br[j];
        }
        __syncthreads();
    }

    #pragma unroll
    for (int i = 0; i < TM; i++) {
        float* crow = C + (size_t)(bm + ty * TM + i) * N + bn + tx * TN;
        *(float4*)(crow + 0) = make_float4(acc[i][0], acc[i][1], acc[i][2], acc[i][3]);
        *(float4*)(crow + 4) = make_float4(acc[i][4], acc[i][5], acc[i][6], acc[i][7]);
    }
}

// ---------------------------------------------------------------------------
// YaRN RoPE applied in-place to Q and K inside g_qkv.
// One thread per (b, t, head, pair). heads 0..15 = Q, 16..19 = K.
// ---------------------------------------------------------------------------
#define ATTN_FACTOR 1.4158883083359672f
#define LG2_BASE 19.931568569324174f   // log2(1e6)

__global__ void rope_kernel(float* __restrict__ qkv) {
    long long idx = (long long)blockIdx.x * blockDim.x + threadIdx.x;
    const long long total = (long long)MROWS * 20 * 64;
    if (idx >= total) return;

    int i   = (int)(idx & 63);           // pair index 0..63
    int hd  = (int)((idx >> 6) % 20);    // head 0..19
    long long bt = idx / (64 * 20);      // 0..MROWS-1
    int t   = (int)(bt % Tsz);

    // YaRN inv_freq: low=23, high=31
    float fi = (float)i;
    float ramp = fminf(fmaxf((fi - 23.0f) * (1.0f / 8.0f), 0.0f), 1.0f);
    float extrap = 1.0f - ramp;
    float pf = exp2f(fi * (LG2_BASE / 64.0f));      // base^(i/64)
    float inv = ramp * (1.0f / (64.0f * pf)) + extrap * (1.0f / pf);

    float angle = (float)t * inv;
    float c = cosf(angle);
    float s = sinf(angle);

    int col = (hd < 16) ? hd * DH : NE + (hd - 16) * DH;
    float* p = qkv + bt * QKV_W + col + 2 * i;
    float xe = p[0], xo = p[1];
    p[0] = (xe * c - xo * s) * ATTN_FACTOR;
    p[1] = (xe * s + xo * c) * ATTN_FACTOR;
}

// ---------------------------------------------------------------------------
// Flash attention (causal, GQA). One block = 64 Q rows of one (b, head).
// 128 threads: thread pair (row, half) — row = tid>>1, half = tid&1 owns
// dims [half*64, half*64+64). Pair lives in the same warp -> shfl combine.
// ---------------------------------------------------------------------------
#define FBM 64     // q rows per block
#define FBN 32     // k rows per smem tile
#define SCALE 0.08838834764831843f   // 1/sqrt(128)

__global__ __launch_bounds__(128)
void flash_attn_kernel(const float* __restrict__ qkv, float* __restrict__ y) {
    __shared__ float Ks[FBN][DH];
    __shared__ float Vs[FBN][DH];

    const int qt = blockIdx.x;          // q tile
    const int bh = blockIdx.y;          // b*NH + head
    const int b  = bh / NH;
    const int hh = bh % NH;
    const int kvh = hh / GQ;

    const float* Qbase = qkv + (size_t)b * Tsz * QKV_W + hh * DH;
    const float* Kbase = qkv + (size_t)b * Tsz * QKV_W + NE + kvh * DH;
    const float* Vbase = qkv + (size_t)b * Tsz * QKV_W + NE + NKV * DH + kvh * DH;

    const int tid = threadIdx.x;
    const int row  = tid >> 1;
    const int half = tid & 1;
    const int qrow = qt * FBM + row;

    float q[64];
    {
        const float* qp = Qbase + (size_t)qrow * QKV_W + half * 64;
        #pragma unroll
        for (int d = 0; d < 64; d++) q[d] = qp[d];
    }

    float acc[64];
    #pragma unroll
    for (int d = 0; d < 64; d++) acc[d] = 0.f;
    float m = -INFINITY, l = 0.f;

    const int kend = qt * FBM + FBM;    // causal: keys < kend

    for (int k0 = 0; k0 < kend; k0 += FBN) {
        __syncthreads();
        for (int idx = tid; idx < FBN * DH; idx += 128) {
            int r = idx >> 7, c = idx & 127;
            Ks[r][c] = Kbase[(size_t)(k0 + r) * QKV_W + c];
            Vs[r][c] = Vbase[(size_t)(k0 + r) * QKV_W + c];
        }
        __syncthreads();

        #pragma unroll 4
        for (int j = 0; j < FBN; j++) {
            float s = 0.f;
            const float4* kr = (const float4*)&Ks[j][half * 64];
            #pragma unroll
            for (int d4 = 0; d4 < 16; d4++) {
                float4 kv = kr[d4];
                s += q[d4 * 4 + 0] * kv.x + q[d4 * 4 + 1] * kv.y
                   + q[d4 * 4 + 2] * kv.z + q[d4 * 4 + 3] * kv.w;
            }
            s += __shfl_xor_sync(0xffffffffu, s, 1);
            s *= SCALE;
            if (k0 + j > qrow) s = -INFINITY;

            float m_new = fmaxf(m, s);
            float alpha = expf(m - m_new);     // first key is never masked
            float p = expf(s - m_new);
            l = l * alpha + p;
            const float4* vr = (const float4*)&Vs[j][half * 64];
            #pragma unroll
            for (int d4 = 0; d4 < 16; d4++) {
                float4 vv = vr[d4];
                acc[d4 * 4 + 0] = acc[d4 * 4 + 0] * alpha + p * vv.x;
                acc[d4 * 4 + 1] = acc[d4 * 4 + 1] * alpha + p * vv.y;
                acc[d4 * 4 + 2] = acc[d4 * 4 + 2] * alpha + p * vv.z;
                acc[d4 * 4 + 3] = acc[d4 * 4 + 3] * alpha + p * vv.w;
            }
            m = m_new;
        }
    }

    float inv_l = 1.0f / l;
    float* yp = y + ((size_t)b * Tsz + qrow) * NE + hh * DH + half * 64;
    #pragma unroll
    for (int d = 0; d < 64; d++) yp[d] = acc[d] * inv_l;
}

// ---------------------------------------------------------------------------
// Launch
// ---------------------------------------------------------------------------
extern "C" void kernel_launch(void* const* d_in, const int* in_sizes, int n_in,
                              void* d_out, int out_size) {
    const float* x     = (const float*)d_in[0];
    const float* w_qkv = (const float*)d_in[1];
    const float* w_o   = (const float*)d_in[2];
    float* out = (float*)d_out;

    float* qkv = nullptr;
    float* y   = nullptr;
    cudaGetSymbolAddress((void**)&qkv, g_qkv);
    cudaGetSymbolAddress((void**)&y,   g_y);

    // 1) QKV projection: [4096,2048] @ [2048,3072]
    {
        dim3 grid(QKV_W / BN, MROWS / BM);
        sgemm_kernel<<<grid, 256>>>(x, w_qkv, qkv, MROWS, QKV_W, NE);
    }

    // 2) RoPE on Q and K (in place)
    {
        long long total = (long long)MROWS * 20 * 64;
        int threads = 256;
        int blocks = (int)((total + threads - 1) / threads);
        rope_kernel<<<blocks, threads>>>(qkv);
    }

    // 3) Causal GQA flash attention -> y [4096, 2048]
    {
        dim3 grid(Tsz / FBM, Bsz * NH);
        flash_attn_kernel<<<grid, 128>>>(qkv, y);
    }

    // 4) Output projection: [4096,2048] @ [2048,2048] -> out
    {
        dim3 grid(NE / BN, MROWS / BM);
        sgemm_kernel<<<grid, 256>>>(y, w_o, out, MROWS, NE, NE);
    }
}